// round 13
// baseline (speedup 1.0000x reference)
#include <cuda_runtime.h>
#include <cuda_fp16.h>
#include <math.h>
#include <stdint.h>

#define Bq   128
#define Tq   512
#define Iq   512
#define Hq   1024
#define G4   4096
#define TGTq 512
#define NB   65536   // Tq * Bq
#define NCTA 128

// ---------------- persistent-kernel SMEM layout (A resident) -------------
#define PA          1032                   // A row pitch (halves): 1024 + 8 pad
#define A_SPL_B     (32 * PA * 2)          // 66048 B
// request >114KB so at most 1 CTA/SM is resident (co-residency insurance)
#define SMEM_PERS   (2 * A_SPL_B + 16)     // 132112 B (only first 66KB used)

// ---------------- xproj GEMM SMEM layout ---------------------------------
#define SP          72
#define REG_BYTES   (128 * SP * 2)         // 18432
#define XBUF_BYTES  (3 * REG_BYTES)        // Ah, Al, Bx
#define SMEM_XP     (2 * XBUF_BYTES)       // 110592 B

// ---------------------------------------------------------------------------
// Persistent device scratch (no cudaMalloc allowed)
// ---------------------------------------------------------------------------
__device__ __align__(16) __half g_Wr_h[(size_t)G4 * Hq];   // Whh fp16 (single)
__device__ __align__(16) __half g_Wi_h[(size_t)G4 * Iq];   // Wih hi
__device__ __align__(16) __half g_Wi_l[(size_t)G4 * Iq];   // Wih lo
__device__ __align__(16) __half g_xh[(size_t)NB * Iq];     // x fp16 [t*128+b][i]
// h in mma-B-fragment layout (fp16 single): [buf][(kb*16+bg)*32+lane] = {r0,r1}
__device__ __align__(16) uint2 g_hB[2][64 * 16 * 32];
__device__ float g_hf[Hq * Bq];                            // [u][b] final h
__device__ float g_xp[(size_t)G4 * NB];                    // x-proj [row][t*128+b]
__device__ unsigned g_prog[NCTA];                          // steps published per CTA

// ---------------------------------------------------------------------------
// PTX helpers (plain sm_100 feature set)
// ---------------------------------------------------------------------------
__device__ __forceinline__ uint32_t smem_u32(const void* p) {
    uint32_t a;
    asm("{ .reg .u64 t; cvta.to.shared.u64 t, %1; cvt.u32.u64 %0, t; }"
        : "=r"(a) : "l"(p));
    return a;
}
__device__ __forceinline__ void ldsm4(uint32_t* r, uint32_t addr) {
    asm volatile("ldmatrix.sync.aligned.m8n8.x4.shared.b16 {%0,%1,%2,%3}, [%4];"
                 : "=r"(r[0]), "=r"(r[1]), "=r"(r[2]), "=r"(r[3]) : "r"(addr));
}
__device__ __forceinline__ void ldsm2(uint32_t* r, uint32_t addr) {
    asm volatile("ldmatrix.sync.aligned.m8n8.x2.shared.b16 {%0,%1}, [%2];"
                 : "=r"(r[0]), "=r"(r[1]) : "r"(addr));
}
__device__ __forceinline__ void mma16816(float* c, const uint32_t* a, const uint32_t* b) {
    asm volatile(
        "mma.sync.aligned.m16n8k16.row.col.f32.f16.f16.f32 "
        "{%0,%1,%2,%3}, {%4,%5,%6,%7}, {%8,%9}, {%0,%1,%2,%3};"
        : "+f"(c[0]), "+f"(c[1]), "+f"(c[2]), "+f"(c[3])
        : "r"(a[0]), "r"(a[1]), "r"(a[2]), "r"(a[3]), "r"(b[0]), "r"(b[1]));
}
__device__ __forceinline__ void ldg_cg_v2(uint2& v, const uint2* p) {
    asm volatile("ld.global.cg.v2.u32 {%0,%1}, [%2];"
                 : "=r"(v.x), "=r"(v.y) : "l"(p));
}
__device__ __forceinline__ unsigned ld_acq(const unsigned* p) {
    unsigned v;
    asm volatile("ld.acquire.gpu.global.u32 %0, [%1];" : "=r"(v) : "l"(p) : "memory");
    return v;
}
#define CP16(d, s) \
    asm volatile("cp.async.cg.shared.global [%0], [%1], 16;" :: "r"(d), "l"(s) : "memory")
#define CPCOMMIT() asm volatile("cp.async.commit_group;" ::: "memory")

__device__ __forceinline__ float sigf(float x) {
    return __fdividef(1.0f, 1.0f + __expf(-x));
}
__device__ __forceinline__ float tanhfast(float x) {
    return __fdividef(2.0f, 1.0f + __expf(-2.0f * x)) - 1.0f;
}

// ---------------------------------------------------------------------------
// Prep kernels
// ---------------------------------------------------------------------------
__global__ void k_prep_w(const float* __restrict__ Wih, const float* __restrict__ Whh) {
    int r = blockIdx.x;
    for (int k = threadIdx.x; k < Hq; k += 256) {
        g_Wr_h[(size_t)r * Hq + k] = __float2half_rn(Whh[(size_t)r * Hq + k]);
    }
    for (int k = threadIdx.x; k < Iq; k += 256) {
        float w = Wih[(size_t)r * Iq + k];
        __half hi = __float2half_rn(w);
        g_Wi_h[(size_t)r * Iq + k] = hi;
        g_Wi_l[(size_t)r * Iq + k] = __float2half_rn(w - __half2float(hi));
    }
}

__global__ void k_prep_x(const float* __restrict__ XW) {
    int bx = blockIdx.x;          // t*128 + b
    int t = bx >> 7, b = bx & 127;
    const float* __restrict__ src = XW + ((size_t)b * Tq + t) * Iq;
    size_t doff = (size_t)bx * Iq;
    for (int i = threadIdx.x; i < Iq; i += 256) {
        g_xh[doff + i] = __float2half_rn(src[i]);
    }
}

__global__ void k_init() {
    if (blockIdx.x == 0 && threadIdx.x < NCTA) g_prog[threadIdx.x] = 0;
    int n = 64 * 16 * 32;
    uint2 z = make_uint2(0, 0);
    for (int i = blockIdx.x * blockDim.x + threadIdx.x; i < n;
         i += gridDim.x * blockDim.x) {
        g_hB[0][i] = z;
        g_hB[1][i] = z;
    }
}

// ---------------------------------------------------------------------------
// x-projection GEMM (fp16 2-term split on W): g_xp = Wih * x^T
// grid (32, 512): C tile 128(M of 4096) x 128(N of 65536), K=512.
// ---------------------------------------------------------------------------
__global__ __launch_bounds__(256) void k_xproj() {
    extern __shared__ __align__(128) uint8_t smem[];
    const uint32_t sb = smem_u32(smem);
    const int tid = threadIdx.x;
    const int L = tid & 31, w = tid >> 5;
    const int mw = w & 3, nw = w >> 2;   // warp tile M32 x N64

    const int mrow0 = blockIdx.x * 128;
    const int nrow0 = blockIdx.y * 128;
    const int lsc = tid & 7;

    const uint32_t a_off = ((mw * 32 + (L & 15)) * SP + (L >> 4) * 8) * 2;
    const uint32_t b_off = ((nw * 64 + (L & 7)) * SP + ((L >> 3) & 1) * 8) * 2;

    float acc[2][8][4];
#pragma unroll
    for (int mi = 0; mi < 2; mi++)
#pragma unroll
        for (int nj = 0; nj < 8; nj++)
#pragma unroll
            for (int q = 0; q < 4; q++) acc[mi][nj][q] = 0.0f;

    auto load_chunk = [&](int buf, int ch) {
        const int gk = ch * 64 + lsc * 8;
        const uint32_t dstbase = sb + buf * XBUF_BYTES;
#pragma unroll
        for (int i = 0; i < 4; i++) {
            int row = (tid >> 3) + i * 32;
            uint32_t doff = (uint32_t)row * 144 + lsc * 16;
            size_t ao = (size_t)(mrow0 + row) * Iq + gk;
            size_t bo = (size_t)(nrow0 + row) * Iq + gk;
            CP16(dstbase + 0 * REG_BYTES + doff, g_Wi_h + ao);
            CP16(dstbase + 1 * REG_BYTES + doff, g_Wi_l + ao);
            CP16(dstbase + 2 * REG_BYTES + doff, g_xh + bo);
        }
        CPCOMMIT();
    };

    load_chunk(0, 0);
    load_chunk(1, 1);
    for (int c = 0; c < 8; c++) {
        if (c < 7) asm volatile("cp.async.wait_group 1;" ::: "memory");
        else       asm volatile("cp.async.wait_group 0;" ::: "memory");
        __syncthreads();
        const uint32_t base = sb + (c & 1) * XBUF_BYTES;
#pragma unroll
        for (int ki = 0; ki < 4; ki++) {
            uint32_t ah[2][4], al[2][4], bh[8][2];
#pragma unroll
            for (int mi = 0; mi < 2; mi++) {
                uint32_t ad = base + a_off + (mi * 16 * SP + ki * 16) * 2;
                ldsm4(ah[mi], ad);
                ldsm4(al[mi], ad + REG_BYTES);
            }
#pragma unroll
            for (int nj = 0; nj < 8; nj++) {
                uint32_t bd = base + 2 * REG_BYTES + b_off + (nj * 8 * SP + ki * 16) * 2;
                ldsm2(bh[nj], bd);
            }
#pragma unroll
            for (int mi = 0; mi < 2; mi++)
#pragma unroll
                for (int nj = 0; nj < 8; nj++) {
                    mma16816(acc[mi][nj], ah[mi], bh[nj]);
                    mma16816(acc[mi][nj], al[mi], bh[nj]);
                }
        }
        if (c + 2 < 8) {
            __syncthreads();
            load_chunk(c & 1, c + 2);
        }
    }

#pragma unroll
    for (int mi = 0; mi < 2; mi++)
#pragma unroll
        for (int nj = 0; nj < 8; nj++) {
            int row = mrow0 + mw * 32 + mi * 16 + (L >> 2);
            int col = nrow0 + nw * 64 + nj * 8 + (L & 3) * 2;
            float* p = g_xp + (size_t)row * NB + col;
            *(float2*)p            = make_float2(acc[mi][nj][0], acc[mi][nj][1]);
            *(float2*)(p + 8 * NB) = make_float2(acc[mi][nj][2], acc[mi][nj][3]);
        }
}

// ---------------------------------------------------------------------------
// Persistent recurrence (R10 shape, flag-synced). CTA c owns units
// u = c*8..c*8+7. A = Whh fp16 resident in SMEM; B (h) via ld.cg.v2
// register ring (depth 3). NO global barrier: per-CTA progress flags,
// per-group acquire-polls, K-groups rotated to start at own slice.
// ---------------------------------------------------------------------------
__global__ __launch_bounds__(256, 1) void k_recur(const float* __restrict__ bih,
                                                  const float* __restrict__ bhh) {
    extern __shared__ __align__(128) uint8_t smem[];
    const uint32_t sb = smem_u32(smem);
    const int tid = threadIdx.x;
    const int c = blockIdx.x;
    const int L = tid & 31;
    const int nw = tid >> 5;             // warp = N group of 16 batch cols

    // ---- load resident A (Whh fp16) : 32 rows x 1024 halves ----
    {
        int row32 = tid >> 3;            // 0..31  (row = g*8 + j)
        int g = row32 >> 3, j = row32 & 7;
        size_t grow = ((size_t)g * Hq + c * 8 + j) * Hq;
        int seg = tid & 7;
#pragma unroll
        for (int it = 0; it < 16; it++) {
            int s16 = seg + it * 8;
            uint32_t doff = (uint32_t)row32 * (PA * 2) + s16 * 16;
            CP16(sb + doff, g_Wr_h + grow + s16 * 8);
        }
        CPCOMMIT();
    }

    // per-thread cell mapping (identical to R10)
    const int j = (L >> 2) & 7;          // unit within CTA
    const int u = c * 8 + j;             // global hidden unit
    const int c0 = nw * 16 + (L & 3) * 2; // cells at c0,c0+1,c0+8,c0+9
    float bias[4], cc[4];
#pragma unroll
    for (int g = 0; g < 4; g++) {
        bias[g] = bih[g * Hq + u] + bhh[g * Hq + u];
        cc[g] = 0.0f;                    // cc indexed by (nj*2+e)
    }

    // producer store mapping for h fragments
    const int p_kb   = u >> 4;
    const int p_ln   = (u >> 1) & 3;
    const int p_boff = ((u >> 3) & 1) * 4 + (u & 1) * 2;

    const uint32_t aoff = (((L & 15) * PA + (L >> 4) * 8)) * 2;
    const int bgBase = nw * 2;
    const int gs = c >> 3;               // own K-group: consume first

    asm volatile("cp.async.wait_group 0;" ::: "memory");
    __syncthreads();

    // xp prefetch for first step
    float2 xpv[4][2];
#pragma unroll
    for (int g = 0; g < 4; g++)
#pragma unroll
        for (int nj = 0; nj < 2; nj++)
            xpv[g][nj] = *(const float2*)&g_xp[(size_t)(g * Hq + u) * NB
                                               + (Tq - 1) * Bq + c0 + nj * 8];

    for (int s = 0; s < Tq; s++) {
        const uint2* __restrict__ hBin = g_hB[s & 1];
        uint2* __restrict__ hBout      = g_hB[(s + 1) & 1];

        float acc[2][2][4];
#pragma unroll
        for (int mi = 0; mi < 2; mi++)
#pragma unroll
            for (int nj = 0; nj < 2; nj++)
#pragma unroll
                for (int q = 0; q < 4; q++) acc[mi][nj][q] = 0.0f;

        uint2 Bp[4][8];   // 4-slot ring (depth 3), compile-time indices only

        // wait: this warp may consume group gg only once its 8 producers
        // have published h for step s. Lanes 0-7 poll one producer each.
#define WAITG(GG)                                                             \
        {                                                                     \
            if (L < 8) {                                                      \
                const unsigned* pp = &g_prog[(GG) * 8 + L];                   \
                while (ld_acq(pp) < (unsigned)s) { }                          \
            }                                                                 \
            __syncwarp();                                                     \
        }

#define LOADB(GG, SLOT)                                                       \
        {                                                                     \
            _Pragma("unroll")                                                 \
            for (int kk = 0; kk < 4; kk++)                                    \
                _Pragma("unroll")                                             \
                for (int nj = 0; nj < 2; nj++)                                \
                    ldg_cg_v2(Bp[SLOT][kk * 2 + nj],                          \
                              hBin + (((GG) * 4 + kk) * 16 + bgBase + nj) * 32 + L); \
        }

        {
            const int g0 = gs, g1 = (gs + 1) & 15, g2 = (gs + 2) & 15;
            WAITG(g0); LOADB(g0, 0);
            WAITG(g1); LOADB(g1, 1);
            WAITG(g2); LOADB(g2, 2);
        }

#pragma unroll
        for (int i = 0; i < 16; i++) {
            if (i + 3 < 16) {
                const int ng = (gs + i + 3) & 15;
                const int ns = (i + 3) & 3;
                WAITG(ng); LOADB(ng, ns);
            }
            const int slot = i & 3;
            const int gg = (gs + i) & 15;
#pragma unroll
            for (int kk = 0; kk < 4; kk++) {
                const int k = (gg * 4 + kk) * 16;
                uint32_t ah[2][4];
#pragma unroll
                for (int mi = 0; mi < 2; mi++) {
                    uint32_t ad = sb + aoff + (uint32_t)(mi * 16 * PA + k) * 2;
                    ldsm4(ah[mi], ad);
                }
#pragma unroll
                for (int nj = 0; nj < 2; nj++) {
                    uint32_t bh[2] = { Bp[slot][kk * 2 + nj].x, Bp[slot][kk * 2 + nj].y };
#pragma unroll
                    for (int mi = 0; mi < 2; mi++) {
                        mma16816(acc[mi][nj], ah[mi], bh);
                    }
                }
            }
        }
#undef LOADB
#undef WAITG

        // ---- register-local cell update for 4 (batch) positions ----
        const bool last = (s == Tq - 1);
#pragma unroll
        for (int nj = 0; nj < 2; nj++)
#pragma unroll
            for (int e = 0; e < 2; e++) {
                int b = c0 + nj * 8 + e;
                float xpi = e ? xpv[0][nj].y : xpv[0][nj].x;
                float xpf = e ? xpv[1][nj].y : xpv[1][nj].x;
                float xpg = e ? xpv[2][nj].y : xpv[2][nj].x;
                float xpo = e ? xpv[3][nj].y : xpv[3][nj].x;
                float ig = sigf(acc[0][nj][e]     + xpi + bias[0]);
                float fg = sigf(acc[0][nj][2 + e] + xpf + bias[1]);
                float gg = tanhfast(acc[1][nj][e]    + xpg + bias[2]);
                float og = sigf(acc[1][nj][2 + e] + xpo + bias[3]);
                int ci = nj * 2 + e;
                float cv = fg * cc[ci] + ig * gg;
                cc[ci] = cv;
                float h = og * tanhfast(cv);
                int lane = ((b & 7) << 2) | p_ln;
                char* qp = (char*)&hBout[(p_kb * 16 + (b >> 3)) * 32 + lane];
                *(__half*)(qp + p_boff) = __float2half_rn(h);
                if (last) g_hf[u * Bq + b] = h;
            }

        // ---- publish: all h stores globally visible, then bump progress ----
        __threadfence();
        __syncthreads();
        if (tid == 0) {
            asm volatile("st.release.gpu.global.u32 [%0], %1;"
                         :: "l"(&g_prog[c]), "r"((unsigned)(s + 1)) : "memory");
        }

        // prefetch next step's xp (overlaps with next step's polls/loads)
        if (!last) {
            const int tn = Tq - 2 - s;
#pragma unroll
            for (int g = 0; g < 4; g++)
#pragma unroll
                for (int nj = 0; nj < 2; nj++)
                    xpv[g][nj] = *(const float2*)&g_xp[(size_t)(g * Hq + u) * NB
                                                       + tn * Bq + c0 + nj * 8];
        }
    }
}

// ---------------------------------------------------------------------------
// Final linear
// ---------------------------------------------------------------------------
__global__ __launch_bounds__(256) void k_lin(const float* __restrict__ Wlin,
                                             const float* __restrict__ blin,
                                             float* __restrict__ out) {
    int gid = blockIdx.x * blockDim.x + threadIdx.x;
    int b = gid & (Bq - 1);
    int tgt = gid >> 7;
    float acc = blin[tgt];
    const float* __restrict__ wrow = Wlin + (size_t)tgt * Hq;
#pragma unroll 8
    for (int k = 0; k < Hq; k++) {
        acc += g_hf[k * Bq + b] * wrow[k];
    }
    out[(size_t)b * TGTq + tgt] = acc;
}

// ---------------------------------------------------------------------------
extern "C" void kernel_launch(void* const* d_in, const int* in_sizes, int n_in,
                              void* d_out, int out_size)
{
    const float* XW   = (const float*)d_in[0];
    const float* Wih  = (const float*)d_in[1];
    const float* Whh  = (const float*)d_in[2];
    const float* bih  = (const float*)d_in[3];
    const float* bhh  = (const float*)d_in[4];
    const float* Wlin = (const float*)d_in[5];
    const float* blin = (const float*)d_in[6];
    float* out = (float*)d_out;

    cudaFuncSetAttribute(k_xproj, cudaFuncAttributeMaxDynamicSharedMemorySize, SMEM_XP);
    cudaFuncSetAttribute(k_recur, cudaFuncAttributeMaxDynamicSharedMemorySize, SMEM_PERS);

    k_prep_w<<<G4, 256>>>(Wih, Whh);
    k_prep_x<<<NB, 256>>>(XW);
    k_init<<<128, 256>>>();
    k_xproj<<<dim3(32, 512, 1), 256, SMEM_XP>>>();
    k_recur<<<NCTA, 256, SMEM_PERS>>>(bih, bhh);
    k_lin<<<(Bq * TGTq) / 256, 256>>>(Wlin, blin, out);
}

// round 14
// speedup vs baseline: 2.4787x; 2.4787x over previous
#include <cuda_runtime.h>
#include <cuda_fp16.h>
#include <math.h>
#include <stdint.h>

#define Bq   128
#define Tq   512
#define Iq   512
#define Hq   1024
#define G4   4096
#define TGTq 512
#define NB   65536   // Tq * Bq
#define NCTA 128

// ---------------- persistent-kernel SMEM layout (A resident) -------------
#define PA          1032                   // A row pitch (halves): 1024 + 8 pad
#define A_SPL_B     (32 * PA * 2)          // 66048 B
// request >114KB so at most 1 CTA/SM is resident (co-residency insurance)
#define SMEM_PERS   (2 * A_SPL_B + 16)     // 132112 B (only first 66KB used)

// ---------------- xproj GEMM SMEM layout (single-fp16 W) -----------------
#define SP          72
#define REG_BYTES   (128 * SP * 2)         // 18432
#define XBUF_BYTES  (2 * REG_BYTES)        // Ah, Bx
#define SMEM_XP     (2 * XBUF_BYTES)       // 73728 B

// ---------------------------------------------------------------------------
// Persistent device scratch (no cudaMalloc allowed)
// ---------------------------------------------------------------------------
__device__ __align__(16) __half g_Wr_h[(size_t)G4 * Hq];   // Whh fp16 (single)
__device__ __align__(16) __half g_Wi_h[(size_t)G4 * Iq];   // Wih fp16 (single)
__device__ __align__(16) __half g_xh[(size_t)NB * Iq];     // x fp16 [t*128+b][i]
// h in mma-B-fragment layout (fp16 single): [buf][(kb*16+bg)*32+lane] = {r0,r1}
__device__ __align__(16) uint2 g_hB[2][64 * 16 * 32];
__device__ float g_hf[Hq * Bq];                            // [u][b] final h
__device__ float g_xp[(size_t)G4 * NB];                    // x-proj [row][t*128+b]
__device__ unsigned g_cnt[8];                              // monotonic group counters
__device__ unsigned g_cnt2;                                // monotonic level-2 counter
__device__ unsigned g_gen;                                 // published step count

// ---------------------------------------------------------------------------
// PTX helpers (plain sm_100 feature set)
// ---------------------------------------------------------------------------
__device__ __forceinline__ uint32_t smem_u32(const void* p) {
    uint32_t a;
    asm("{ .reg .u64 t; cvta.to.shared.u64 t, %1; cvt.u32.u64 %0, t; }"
        : "=r"(a) : "l"(p));
    return a;
}
__device__ __forceinline__ void ldsm4(uint32_t* r, uint32_t addr) {
    asm volatile("ldmatrix.sync.aligned.m8n8.x4.shared.b16 {%0,%1,%2,%3}, [%4];"
                 : "=r"(r[0]), "=r"(r[1]), "=r"(r[2]), "=r"(r[3]) : "r"(addr));
}
__device__ __forceinline__ void ldsm2(uint32_t* r, uint32_t addr) {
    asm volatile("ldmatrix.sync.aligned.m8n8.x2.shared.b16 {%0,%1}, [%2];"
                 : "=r"(r[0]), "=r"(r[1]) : "r"(addr));
}
__device__ __forceinline__ void mma16816(float* c, const uint32_t* a, const uint32_t* b) {
    asm volatile(
        "mma.sync.aligned.m16n8k16.row.col.f32.f16.f16.f32 "
        "{%0,%1,%2,%3}, {%4,%5,%6,%7}, {%8,%9}, {%0,%1,%2,%3};"
        : "+f"(c[0]), "+f"(c[1]), "+f"(c[2]), "+f"(c[3])
        : "r"(a[0]), "r"(a[1]), "r"(a[2]), "r"(a[3]), "r"(b[0]), "r"(b[1]));
}
__device__ __forceinline__ void ldg_cg_v2(uint2& v, const uint2* p) {
    asm volatile("ld.global.cg.v2.u32 {%0,%1}, [%2];"
                 : "=r"(v.x), "=r"(v.y) : "l"(p));
}
__device__ __forceinline__ unsigned ld_acq(const unsigned* p) {
    unsigned v;
    asm volatile("ld.acquire.gpu.global.u32 %0, [%1];" : "=r"(v) : "l"(p) : "memory");
    return v;
}
#define CP16(d, s) \
    asm volatile("cp.async.cg.shared.global [%0], [%1], 16;" :: "r"(d), "l"(s) : "memory")
#define CPCOMMIT() asm volatile("cp.async.commit_group;" ::: "memory")

__device__ __forceinline__ float sigf(float x) {
    return __fdividef(1.0f, 1.0f + __expf(-x));
}
__device__ __forceinline__ float tanhfast(float x) {
    return __fdividef(2.0f, 1.0f + __expf(-2.0f * x)) - 1.0f;
}

// ---------------------------------------------------------------------------
// Prep kernels
// ---------------------------------------------------------------------------
__global__ void k_prep_w(const float* __restrict__ Wih, const float* __restrict__ Whh) {
    int r = blockIdx.x;
    for (int k = threadIdx.x; k < Hq; k += 256) {
        g_Wr_h[(size_t)r * Hq + k] = __float2half_rn(Whh[(size_t)r * Hq + k]);
    }
    for (int k = threadIdx.x; k < Iq; k += 256) {
        g_Wi_h[(size_t)r * Iq + k] = __float2half_rn(Wih[(size_t)r * Iq + k]);
    }
}

__global__ void k_prep_x(const float* __restrict__ XW) {
    int bx = blockIdx.x;          // t*128 + b
    int t = bx >> 7, b = bx & 127;
    const float* __restrict__ src = XW + ((size_t)b * Tq + t) * Iq;
    size_t doff = (size_t)bx * Iq;
    for (int i = threadIdx.x; i < Iq; i += 256) {
        g_xh[doff + i] = __float2half_rn(src[i]);
    }
}

__global__ void k_init() {
    if (blockIdx.x == 0 && threadIdx.x < 8) g_cnt[threadIdx.x] = 0;
    if (blockIdx.x == 0 && threadIdx.x == 8) { g_cnt2 = 0; g_gen = 0; }
    int n = 64 * 16 * 32;
    uint2 z = make_uint2(0, 0);
    for (int i = blockIdx.x * blockDim.x + threadIdx.x; i < n;
         i += gridDim.x * blockDim.x) {
        g_hB[0][i] = z;
        g_hB[1][i] = z;
    }
}

// ---------------------------------------------------------------------------
// x-projection GEMM (single fp16): g_xp = Wih * x^T
// grid (32, 512): C tile 128(M of 4096) x 128(N of 65536), K=512.
// ---------------------------------------------------------------------------
__global__ __launch_bounds__(256) void k_xproj() {
    extern __shared__ __align__(128) uint8_t smem[];
    const uint32_t sb = smem_u32(smem);
    const int tid = threadIdx.x;
    const int L = tid & 31, w = tid >> 5;
    const int mw = w & 3, nw = w >> 2;   // warp tile M32 x N64

    const int mrow0 = blockIdx.x * 128;
    const int nrow0 = blockIdx.y * 128;
    const int lsc = tid & 7;

    const uint32_t a_off = ((mw * 32 + (L & 15)) * SP + (L >> 4) * 8) * 2;
    const uint32_t b_off = ((nw * 64 + (L & 7)) * SP + ((L >> 3) & 1) * 8) * 2;

    float acc[2][8][4];
#pragma unroll
    for (int mi = 0; mi < 2; mi++)
#pragma unroll
        for (int nj = 0; nj < 8; nj++)
#pragma unroll
            for (int q = 0; q < 4; q++) acc[mi][nj][q] = 0.0f;

    auto load_chunk = [&](int buf, int ch) {
        const int gk = ch * 64 + lsc * 8;
        const uint32_t dstbase = sb + buf * XBUF_BYTES;
#pragma unroll
        for (int i = 0; i < 4; i++) {
            int row = (tid >> 3) + i * 32;
            uint32_t doff = (uint32_t)row * 144 + lsc * 16;
            size_t ao = (size_t)(mrow0 + row) * Iq + gk;
            size_t bo = (size_t)(nrow0 + row) * Iq + gk;
            CP16(dstbase + 0 * REG_BYTES + doff, g_Wi_h + ao);
            CP16(dstbase + 1 * REG_BYTES + doff, g_xh + bo);
        }
        CPCOMMIT();
    };

    load_chunk(0, 0);
    load_chunk(1, 1);
    for (int c = 0; c < 8; c++) {
        if (c < 7) asm volatile("cp.async.wait_group 1;" ::: "memory");
        else       asm volatile("cp.async.wait_group 0;" ::: "memory");
        __syncthreads();
        const uint32_t base = sb + (c & 1) * XBUF_BYTES;
#pragma unroll
        for (int ki = 0; ki < 4; ki++) {
            uint32_t ah[2][4], bh[8][2];
#pragma unroll
            for (int mi = 0; mi < 2; mi++) {
                uint32_t ad = base + a_off + (mi * 16 * SP + ki * 16) * 2;
                ldsm4(ah[mi], ad);
            }
#pragma unroll
            for (int nj = 0; nj < 8; nj++) {
                uint32_t bd = base + 1 * REG_BYTES + b_off + (nj * 8 * SP + ki * 16) * 2;
                ldsm2(bh[nj], bd);
            }
#pragma unroll
            for (int mi = 0; mi < 2; mi++)
#pragma unroll
                for (int nj = 0; nj < 8; nj++) {
                    mma16816(acc[mi][nj], ah[mi], bh[nj]);
                }
        }
        if (c + 2 < 8) {
            __syncthreads();
            load_chunk(c & 1, c + 2);
        }
    }

#pragma unroll
    for (int mi = 0; mi < 2; mi++)
#pragma unroll
        for (int nj = 0; nj < 8; nj++) {
            int row = mrow0 + mw * 32 + mi * 16 + (L >> 2);
            int col = nrow0 + nw * 64 + nj * 8 + (L & 3) * 2;
            float* p = g_xp + (size_t)row * NB + col;
            *(float2*)p            = make_float2(acc[mi][nj][0], acc[mi][nj][1]);
            *(float2*)(p + 8 * NB) = make_float2(acc[mi][nj][2], acc[mi][nj][3]);
        }
}

// ---------------------------------------------------------------------------
// Persistent recurrence (R10 structure; split monotonic barrier).
// CTA c owns units u = c*8..c*8+7 (32 gate rows). A = Whh fp16 resident
// in SMEM; B (h) via ld.cg.v2 register ring (depth 3). Cell state in
// registers; next h written in B-fragment layout. Barrier: arrive after
// h-publish, xp prefetch in the window, wait just before next step.
// ---------------------------------------------------------------------------
__global__ __launch_bounds__(256, 1) void k_recur(const float* __restrict__ bih,
                                                  const float* __restrict__ bhh) {
    extern __shared__ __align__(128) uint8_t smem[];
    const uint32_t sb = smem_u32(smem);
    const int tid = threadIdx.x;
    const int c = blockIdx.x;
    const int L = tid & 31;
    const int nw = tid >> 5;             // warp = N group of 16 batch cols

    // ---- load resident A (Whh fp16) : 32 rows x 1024 halves ----
    {
        int row32 = tid >> 3;            // 0..31  (row = g*8 + j)
        int g = row32 >> 3, j = row32 & 7;
        size_t grow = ((size_t)g * Hq + c * 8 + j) * Hq;
        int seg = tid & 7;
#pragma unroll
        for (int it = 0; it < 16; it++) {
            int s16 = seg + it * 8;
            uint32_t doff = (uint32_t)row32 * (PA * 2) + s16 * 16;
            CP16(sb + doff, g_Wr_h + grow + s16 * 8);
        }
        CPCOMMIT();
    }

    // per-thread cell mapping (identical to R10)
    const int j = (L >> 2) & 7;          // unit within CTA
    const int u = c * 8 + j;             // global hidden unit
    const int c0 = nw * 16 + (L & 3) * 2; // cells at c0,c0+1,c0+8,c0+9
    float bias[4], cc[4];
#pragma unroll
    for (int g = 0; g < 4; g++) {
        bias[g] = bih[g * Hq + u] + bhh[g * Hq + u];
        cc[g] = 0.0f;                    // cc indexed by (nj*2+e)
    }

    // producer store mapping for h fragments
    const int p_kb   = u >> 4;
    const int p_ln   = (u >> 1) & 3;
    const int p_boff = ((u >> 3) & 1) * 4 + (u & 1) * 2;

    const uint32_t aoff = (((L & 15) * PA + (L >> 4) * 8)) * 2;
    const int bgBase = nw * 2;

    asm volatile("cp.async.wait_group 0;" ::: "memory");
    __syncthreads();

    // xp prefetch for first step
    float2 xpv[4][2];
#pragma unroll
    for (int g = 0; g < 4; g++)
#pragma unroll
        for (int nj = 0; nj < 2; nj++)
            xpv[g][nj] = *(const float2*)&g_xp[(size_t)(g * Hq + u) * NB
                                               + (Tq - 1) * Bq + c0 + nj * 8];

    for (int s = 0; s < Tq; s++) {
        const uint2* __restrict__ hBin = g_hB[s & 1];
        uint2* __restrict__ hBout      = g_hB[(s + 1) & 1];

        float acc[2][2][4];
#pragma unroll
        for (int mi = 0; mi < 2; mi++)
#pragma unroll
            for (int nj = 0; nj < 2; nj++)
#pragma unroll
                for (int q = 0; q < 4; q++) acc[mi][nj][q] = 0.0f;

        uint2 Bp[4][8];   // 4-slot ring (depth 3), compile-time indices only

#define LOADB(G, SLOT)                                                        \
        {                                                                     \
            _Pragma("unroll")                                                 \
            for (int kk = 0; kk < 4; kk++)                                    \
                _Pragma("unroll")                                             \
                for (int nj = 0; nj < 2; nj++)                                \
                    ldg_cg_v2(Bp[SLOT][kk * 2 + nj],                          \
                              hBin + (((G) * 4 + kk) * 16 + bgBase + nj) * 32 + L); \
        }

        LOADB(0, 0); LOADB(1, 1); LOADB(2, 2);

#pragma unroll
        for (int g = 0; g < 16; g++) {
            if (g + 3 < 16) {
                const int ng = g + 3;
                const int ns = ng & 3;
                LOADB(ng, ns);
            }
            const int slot = g & 3;
#pragma unroll
            for (int kk = 0; kk < 4; kk++) {
                const int k = (g * 4 + kk) * 16;
                uint32_t ah[2][4];
#pragma unroll
                for (int mi = 0; mi < 2; mi++) {
                    uint32_t ad = sb + aoff + (uint32_t)(mi * 16 * PA + k) * 2;
                    ldsm4(ah[mi], ad);
                }
#pragma unroll
                for (int nj = 0; nj < 2; nj++) {
                    uint32_t bh[2] = { Bp[slot][kk * 2 + nj].x, Bp[slot][kk * 2 + nj].y };
#pragma unroll
                    for (int mi = 0; mi < 2; mi++) {
                        mma16816(acc[mi][nj], ah[mi], bh);
                    }
                }
            }
        }
#undef LOADB

        // ---- register-local cell update for 4 (batch) positions ----
        const bool last = (s == Tq - 1);
#pragma unroll
        for (int nj = 0; nj < 2; nj++)
#pragma unroll
            for (int e = 0; e < 2; e++) {
                int b = c0 + nj * 8 + e;
                float xpi = e ? xpv[0][nj].y : xpv[0][nj].x;
                float xpf = e ? xpv[1][nj].y : xpv[1][nj].x;
                float xpg = e ? xpv[2][nj].y : xpv[2][nj].x;
                float xpo = e ? xpv[3][nj].y : xpv[3][nj].x;
                float ig = sigf(acc[0][nj][e]     + xpi + bias[0]);
                float fg = sigf(acc[0][nj][2 + e] + xpf + bias[1]);
                float gg = tanhfast(acc[1][nj][e]    + xpg + bias[2]);
                float og = sigf(acc[1][nj][2 + e] + xpo + bias[3]);
                int ci = nj * 2 + e;
                float cv = fg * cc[ci] + ig * gg;
                cc[ci] = cv;
                float h = og * tanhfast(cv);
                int lane = ((b & 7) << 2) | p_ln;
                char* qp = (char*)&hBout[(p_kb * 16 + (b >> 3)) * 32 + lane];
                *(__half*)(qp + p_boff) = __float2half_rn(h);
                if (last) g_hf[u * Bq + b] = h;
            }

        if (!last) {
            // ---- arrive: h stores visible, bump monotonic counters ----
            __threadfence();
            __syncthreads();
            if (tid == 0) {
                unsigned grp = (unsigned)c >> 4;
                unsigned old = atomicAdd(&g_cnt[grp], 1u);
                if ((old & 15u) == 15u) {
                    unsigned o2 = atomicAdd(&g_cnt2, 1u);
                    if ((o2 & 7u) == 7u) {
                        asm volatile("st.release.gpu.global.u32 [%0], %1;"
                                     :: "l"(&g_gen), "r"((unsigned)(s + 1)) : "memory");
                    }
                }
            }

            // ---- overlap window: next step's xp prefetch ----
            const int tn = Tq - 2 - s;
#pragma unroll
            for (int g = 0; g < 4; g++)
#pragma unroll
                for (int nj = 0; nj < 2; nj++)
                    xpv[g][nj] = *(const float2*)&g_xp[(size_t)(g * Hq + u) * NB
                                                       + tn * Bq + c0 + nj * 8];

            // ---- wait: all CTAs published step s+1 ----
            if (tid == 0) {
                while (ld_acq(&g_gen) < (unsigned)(s + 1)) { }
            }
            __syncthreads();
        }
    }
}

// ---------------------------------------------------------------------------
// Final linear
// ---------------------------------------------------------------------------
__global__ __launch_bounds__(256) void k_lin(const float* __restrict__ Wlin,
                                             const float* __restrict__ blin,
                                             float* __restrict__ out) {
    int gid = blockIdx.x * blockDim.x + threadIdx.x;
    int b = gid & (Bq - 1);
    int tgt = gid >> 7;
    float acc = blin[tgt];
    const float* __restrict__ wrow = Wlin + (size_t)tgt * Hq;
#pragma unroll 8
    for (int k = 0; k < Hq; k++) {
        acc += g_hf[k * Bq + b] * wrow[k];
    }
    out[(size_t)b * TGTq + tgt] = acc;
}

// ---------------------------------------------------------------------------
extern "C" void kernel_launch(void* const* d_in, const int* in_sizes, int n_in,
                              void* d_out, int out_size)
{
    const float* XW   = (const float*)d_in[0];
    const float* Wih  = (const float*)d_in[1];
    const float* Whh  = (const float*)d_in[2];
    const float* bih  = (const float*)d_in[3];
    const float* bhh  = (const float*)d_in[4];
    const float* Wlin = (const float*)d_in[5];
    const float* blin = (const float*)d_in[6];
    float* out = (float*)d_out;

    cudaFuncSetAttribute(k_xproj, cudaFuncAttributeMaxDynamicSharedMemorySize, SMEM_XP);
    cudaFuncSetAttribute(k_recur, cudaFuncAttributeMaxDynamicSharedMemorySize, SMEM_PERS);

    k_prep_w<<<G4, 256>>>(Wih, Whh);
    k_prep_x<<<NB, 256>>>(XW);
    k_init<<<128, 256>>>();
    k_xproj<<<dim3(32, 512, 1), 256, SMEM_XP>>>();
    k_recur<<<NCTA, 256, SMEM_PERS>>>(bih, bhh);
    k_lin<<<(Bq * TGTq) / 256, 256>>>(Wlin, blin, out);
}

// round 15
// speedup vs baseline: 2.5056x; 1.0109x over previous
#include <cuda_runtime.h>
#include <cuda_fp16.h>
#include <math.h>
#include <stdint.h>

#define Bq   128
#define Tq   512
#define Iq   512
#define Hq   1024
#define G4   4096
#define TGTq 512
#define NB   65536   // Tq * Bq
#define NCTA 128

// ---------------- persistent-kernel SMEM layout (A resident) -------------
#define PA          1032                   // A row pitch (halves): 1024 + 8 pad
#define A_SPL_B     (32 * PA * 2)          // 66048 B
// request >114KB so at most 1 CTA/SM is resident (co-residency insurance)
#define SMEM_PERS   (2 * A_SPL_B + 16)     // 132112 B (only first 66KB used)

// ---------------- xproj GEMM SMEM layout (single-fp16 W) -----------------
#define SP          72
#define REG_BYTES   (128 * SP * 2)         // 18432
#define XBUF_BYTES  (2 * REG_BYTES)        // Ah, Bx
#define SMEM_XP     (2 * XBUF_BYTES)       // 73728 B

// ---------------------------------------------------------------------------
// Persistent device scratch (no cudaMalloc allowed)
// ---------------------------------------------------------------------------
__device__ __align__(16) __half g_Wr_h[(size_t)G4 * Hq];   // Whh fp16 (single)
__device__ __align__(16) __half g_Wi_h[(size_t)G4 * Iq];   // Wih fp16 (single)
__device__ __align__(16) __half g_xh[(size_t)NB * Iq];     // x fp16 [t*128+b][i]
// h in mma-B-fragment layout (fp16 single): [buf][(kb*16+bg)*32+lane] = {r0,r1}
__device__ __align__(16) uint2 g_hB[2][64 * 16 * 32];
__device__ float g_hf[Hq * Bq];                            // [u][b] final h
__device__ __align__(16) __half g_xp16[(size_t)G4 * NB];   // x-proj fp16 [row][t*128+b]
__device__ unsigned g_cnt[8];                              // monotonic group counters
__device__ unsigned g_cnt2;                                // monotonic level-2 counter
__device__ unsigned g_gen;                                 // published step count

// ---------------------------------------------------------------------------
// PTX helpers (plain sm_100 feature set)
// ---------------------------------------------------------------------------
__device__ __forceinline__ uint32_t smem_u32(const void* p) {
    uint32_t a;
    asm("{ .reg .u64 t; cvta.to.shared.u64 t, %1; cvt.u32.u64 %0, t; }"
        : "=r"(a) : "l"(p));
    return a;
}
__device__ __forceinline__ void ldsm4(uint32_t* r, uint32_t addr) {
    asm volatile("ldmatrix.sync.aligned.m8n8.x4.shared.b16 {%0,%1,%2,%3}, [%4];"
                 : "=r"(r[0]), "=r"(r[1]), "=r"(r[2]), "=r"(r[3]) : "r"(addr));
}
__device__ __forceinline__ void ldsm2(uint32_t* r, uint32_t addr) {
    asm volatile("ldmatrix.sync.aligned.m8n8.x2.shared.b16 {%0,%1}, [%2];"
                 : "=r"(r[0]), "=r"(r[1]) : "r"(addr));
}
__device__ __forceinline__ void mma16816(float* c, const uint32_t* a, const uint32_t* b) {
    asm volatile(
        "mma.sync.aligned.m16n8k16.row.col.f32.f16.f16.f32 "
        "{%0,%1,%2,%3}, {%4,%5,%6,%7}, {%8,%9}, {%0,%1,%2,%3};"
        : "+f"(c[0]), "+f"(c[1]), "+f"(c[2]), "+f"(c[3])
        : "r"(a[0]), "r"(a[1]), "r"(a[2]), "r"(a[3]), "r"(b[0]), "r"(b[1]));
}
__device__ __forceinline__ void ldg_cg_v2(uint2& v, const uint2* p) {
    asm volatile("ld.global.cg.v2.u32 {%0,%1}, [%2];"
                 : "=r"(v.x), "=r"(v.y) : "l"(p));
}
__device__ __forceinline__ unsigned ld_acq(const unsigned* p) {
    unsigned v;
    asm volatile("ld.acquire.gpu.global.u32 %0, [%1];" : "=r"(v) : "l"(p) : "memory");
    return v;
}
#define CP16(d, s) \
    asm volatile("cp.async.cg.shared.global [%0], [%1], 16;" :: "r"(d), "l"(s) : "memory")
#define CPCOMMIT() asm volatile("cp.async.commit_group;" ::: "memory")

__device__ __forceinline__ float sigf(float x) {
    return __fdividef(1.0f, 1.0f + __expf(-x));
}
__device__ __forceinline__ float tanhfast(float x) {
    return __fdividef(2.0f, 1.0f + __expf(-2.0f * x)) - 1.0f;
}

// ---------------------------------------------------------------------------
// Prep kernels
// ---------------------------------------------------------------------------
__global__ void k_prep_w(const float* __restrict__ Wih, const float* __restrict__ Whh) {
    int r = blockIdx.x;
    for (int k = threadIdx.x; k < Hq; k += 256) {
        g_Wr_h[(size_t)r * Hq + k] = __float2half_rn(Whh[(size_t)r * Hq + k]);
    }
    for (int k = threadIdx.x; k < Iq; k += 256) {
        g_Wi_h[(size_t)r * Iq + k] = __float2half_rn(Wih[(size_t)r * Iq + k]);
    }
}

__global__ void k_prep_x(const float* __restrict__ XW) {
    int bx = blockIdx.x;          // t*128 + b
    int t = bx >> 7, b = bx & 127;
    const float* __restrict__ src = XW + ((size_t)b * Tq + t) * Iq;
    size_t doff = (size_t)bx * Iq;
    for (int i = threadIdx.x; i < Iq; i += 256) {
        g_xh[doff + i] = __float2half_rn(src[i]);
    }
}

__global__ void k_init() {
    if (blockIdx.x == 0 && threadIdx.x < 8) g_cnt[threadIdx.x] = 0;
    if (blockIdx.x == 0 && threadIdx.x == 8) { g_cnt2 = 0; g_gen = 0; }
    int n = 64 * 16 * 32;
    uint2 z = make_uint2(0, 0);
    for (int i = blockIdx.x * blockDim.x + threadIdx.x; i < n;
         i += gridDim.x * blockDim.x) {
        g_hB[0][i] = z;
        g_hB[1][i] = z;
    }
}

// ---------------------------------------------------------------------------
// x-projection GEMM (single fp16): g_xp16 = fp16(Wih * x^T)
// grid (32, 512): C tile 128(M of 4096) x 128(N of 65536), K=512.
// Output stored fp16 with streaming stores (no reuse in this kernel).
// ---------------------------------------------------------------------------
__global__ __launch_bounds__(256) void k_xproj() {
    extern __shared__ __align__(128) uint8_t smem[];
    const uint32_t sb = smem_u32(smem);
    const int tid = threadIdx.x;
    const int L = tid & 31, w = tid >> 5;
    const int mw = w & 3, nw = w >> 2;   // warp tile M32 x N64

    const int mrow0 = blockIdx.x * 128;
    const int nrow0 = blockIdx.y * 128;
    const int lsc = tid & 7;

    const uint32_t a_off = ((mw * 32 + (L & 15)) * SP + (L >> 4) * 8) * 2;
    const uint32_t b_off = ((nw * 64 + (L & 7)) * SP + ((L >> 3) & 1) * 8) * 2;

    float acc[2][8][4];
#pragma unroll
    for (int mi = 0; mi < 2; mi++)
#pragma unroll
        for (int nj = 0; nj < 8; nj++)
#pragma unroll
            for (int q = 0; q < 4; q++) acc[mi][nj][q] = 0.0f;

    auto load_chunk = [&](int buf, int ch) {
        const int gk = ch * 64 + lsc * 8;
        const uint32_t dstbase = sb + buf * XBUF_BYTES;
#pragma unroll
        for (int i = 0; i < 4; i++) {
            int row = (tid >> 3) + i * 32;
            uint32_t doff = (uint32_t)row * 144 + lsc * 16;
            size_t ao = (size_t)(mrow0 + row) * Iq + gk;
            size_t bo = (size_t)(nrow0 + row) * Iq + gk;
            CP16(dstbase + 0 * REG_BYTES + doff, g_Wi_h + ao);
            CP16(dstbase + 1 * REG_BYTES + doff, g_xh + bo);
        }
        CPCOMMIT();
    };

    load_chunk(0, 0);
    load_chunk(1, 1);
    for (int c = 0; c < 8; c++) {
        if (c < 7) asm volatile("cp.async.wait_group 1;" ::: "memory");
        else       asm volatile("cp.async.wait_group 0;" ::: "memory");
        __syncthreads();
        const uint32_t base = sb + (c & 1) * XBUF_BYTES;
#pragma unroll
        for (int ki = 0; ki < 4; ki++) {
            uint32_t ah[2][4], bh[8][2];
#pragma unroll
            for (int mi = 0; mi < 2; mi++) {
                uint32_t ad = base + a_off + (mi * 16 * SP + ki * 16) * 2;
                ldsm4(ah[mi], ad);
            }
#pragma unroll
            for (int nj = 0; nj < 8; nj++) {
                uint32_t bd = base + 1 * REG_BYTES + b_off + (nj * 8 * SP + ki * 16) * 2;
                ldsm2(bh[nj], bd);
            }
#pragma unroll
            for (int mi = 0; mi < 2; mi++)
#pragma unroll
                for (int nj = 0; nj < 8; nj++) {
                    mma16816(acc[mi][nj], ah[mi], bh[nj]);
                }
        }
        if (c + 2 < 8) {
            __syncthreads();
            load_chunk(c & 1, c + 2);
        }
    }

#pragma unroll
    for (int mi = 0; mi < 2; mi++)
#pragma unroll
        for (int nj = 0; nj < 8; nj++) {
            int row = mrow0 + mw * 32 + mi * 16 + (L >> 2);
            int col = nrow0 + nw * 64 + nj * 8 + (L & 3) * 2;
            __half* p = g_xp16 + (size_t)row * NB + col;
            __stcs((__half2*)p,
                   __floats2half2_rn(acc[mi][nj][0], acc[mi][nj][1]));
            __stcs((__half2*)(p + 8 * NB),
                   __floats2half2_rn(acc[mi][nj][2], acc[mi][nj][3]));
        }
}

// ---------------------------------------------------------------------------
// Persistent recurrence (R14 structure, fp16 xp reads).
// CTA c owns units u = c*8..c*8+7 (32 gate rows). A = Whh fp16 resident
// in SMEM; B (h) via ld.cg.v2 register ring (depth 3). Cell state in
// registers; next h written in B-fragment layout. Barrier: arrive after
// h-publish, xp prefetch in the window, wait just before next step.
// ---------------------------------------------------------------------------
__global__ __launch_bounds__(256, 1) void k_recur(const float* __restrict__ bih,
                                                  const float* __restrict__ bhh) {
    extern __shared__ __align__(128) uint8_t smem[];
    const uint32_t sb = smem_u32(smem);
    const int tid = threadIdx.x;
    const int c = blockIdx.x;
    const int L = tid & 31;
    const int nw = tid >> 5;             // warp = N group of 16 batch cols

    // ---- load resident A (Whh fp16) : 32 rows x 1024 halves ----
    {
        int row32 = tid >> 3;            // 0..31  (row = g*8 + j)
        int g = row32 >> 3, j = row32 & 7;
        size_t grow = ((size_t)g * Hq + c * 8 + j) * Hq;
        int seg = tid & 7;
#pragma unroll
        for (int it = 0; it < 16; it++) {
            int s16 = seg + it * 8;
            uint32_t doff = (uint32_t)row32 * (PA * 2) + s16 * 16;
            CP16(sb + doff, g_Wr_h + grow + s16 * 8);
        }
        CPCOMMIT();
    }

    // per-thread cell mapping (identical to R10/R14)
    const int j = (L >> 2) & 7;          // unit within CTA
    const int u = c * 8 + j;             // global hidden unit
    const int c0 = nw * 16 + (L & 3) * 2; // cells at c0,c0+1,c0+8,c0+9
    float bias[4], cc[4];
#pragma unroll
    for (int g = 0; g < 4; g++) {
        bias[g] = bih[g * Hq + u] + bhh[g * Hq + u];
        cc[g] = 0.0f;                    // cc indexed by (nj*2+e)
    }

    // producer store mapping for h fragments
    const int p_kb   = u >> 4;
    const int p_ln   = (u >> 1) & 3;
    const int p_boff = ((u >> 3) & 1) * 4 + (u & 1) * 2;

    const uint32_t aoff = (((L & 15) * PA + (L >> 4) * 8)) * 2;
    const int bgBase = nw * 2;

    asm volatile("cp.async.wait_group 0;" ::: "memory");
    __syncthreads();

    // xp prefetch for first step (fp16 pairs)
    __half2 xph[4][2];
#pragma unroll
    for (int g = 0; g < 4; g++)
#pragma unroll
        for (int nj = 0; nj < 2; nj++)
            xph[g][nj] = *(const __half2*)&g_xp16[(size_t)(g * Hq + u) * NB
                                                  + (Tq - 1) * Bq + c0 + nj * 8];

    for (int s = 0; s < Tq; s++) {
        const uint2* __restrict__ hBin = g_hB[s & 1];
        uint2* __restrict__ hBout      = g_hB[(s + 1) & 1];

        float acc[2][2][4];
#pragma unroll
        for (int mi = 0; mi < 2; mi++)
#pragma unroll
            for (int nj = 0; nj < 2; nj++)
#pragma unroll
                for (int q = 0; q < 4; q++) acc[mi][nj][q] = 0.0f;

        uint2 Bp[4][8];   // 4-slot ring (depth 3), compile-time indices only

#define LOADB(G, SLOT)                                                        \
        {                                                                     \
            _Pragma("unroll")                                                 \
            for (int kk = 0; kk < 4; kk++)                                    \
                _Pragma("unroll")                                             \
                for (int nj = 0; nj < 2; nj++)                                \
                    ldg_cg_v2(Bp[SLOT][kk * 2 + nj],                          \
                              hBin + (((G) * 4 + kk) * 16 + bgBase + nj) * 32 + L); \
        }

        LOADB(0, 0); LOADB(1, 1); LOADB(2, 2);

#pragma unroll
        for (int g = 0; g < 16; g++) {
            if (g + 3 < 16) {
                const int ng = g + 3;
                const int ns = ng & 3;
                LOADB(ng, ns);
            }
            const int slot = g & 3;
#pragma unroll
            for (int kk = 0; kk < 4; kk++) {
                const int k = (g * 4 + kk) * 16;
                uint32_t ah[2][4];
#pragma unroll
                for (int mi = 0; mi < 2; mi++) {
                    uint32_t ad = sb + aoff + (uint32_t)(mi * 16 * PA + k) * 2;
                    ldsm4(ah[mi], ad);
                }
#pragma unroll
                for (int nj = 0; nj < 2; nj++) {
                    uint32_t bh[2] = { Bp[slot][kk * 2 + nj].x, Bp[slot][kk * 2 + nj].y };
#pragma unroll
                    for (int mi = 0; mi < 2; mi++) {
                        mma16816(acc[mi][nj], ah[mi], bh);
                    }
                }
            }
        }
#undef LOADB

        // ---- register-local cell update for 4 (batch) positions ----
        const bool last = (s == Tq - 1);
#pragma unroll
        for (int nj = 0; nj < 2; nj++) {
            float2 x0 = __half22float2(xph[0][nj]);
            float2 x1 = __half22float2(xph[1][nj]);
            float2 x2 = __half22float2(xph[2][nj]);
            float2 x3 = __half22float2(xph[3][nj]);
#pragma unroll
            for (int e = 0; e < 2; e++) {
                int b = c0 + nj * 8 + e;
                float xpi = e ? x0.y : x0.x;
                float xpf = e ? x1.y : x1.x;
                float xpg = e ? x2.y : x2.x;
                float xpo = e ? x3.y : x3.x;
                float ig = sigf(acc[0][nj][e]     + xpi + bias[0]);
                float fg = sigf(acc[0][nj][2 + e] + xpf + bias[1]);
                float gg = tanhfast(acc[1][nj][e]    + xpg + bias[2]);
                float og = sigf(acc[1][nj][2 + e] + xpo + bias[3]);
                int ci = nj * 2 + e;
                float cv = fg * cc[ci] + ig * gg;
                cc[ci] = cv;
                float h = og * tanhfast(cv);
                int lane = ((b & 7) << 2) | p_ln;
                char* qp = (char*)&hBout[(p_kb * 16 + (b >> 3)) * 32 + lane];
                *(__half*)(qp + p_boff) = __float2half_rn(h);
                if (last) g_hf[u * Bq + b] = h;
            }
        }

        if (!last) {
            // ---- arrive: h stores visible, bump monotonic counters ----
            __threadfence();
            __syncthreads();
            if (tid == 0) {
                unsigned grp = (unsigned)c >> 4;
                unsigned old = atomicAdd(&g_cnt[grp], 1u);
                if ((old & 15u) == 15u) {
                    unsigned o2 = atomicAdd(&g_cnt2, 1u);
                    if ((o2 & 7u) == 7u) {
                        asm volatile("st.release.gpu.global.u32 [%0], %1;"
                                     :: "l"(&g_gen), "r"((unsigned)(s + 1)) : "memory");
                    }
                }
            }

            // ---- overlap window: next step's xp prefetch (fp16) ----
            const int tn = Tq - 2 - s;
#pragma unroll
            for (int g = 0; g < 4; g++)
#pragma unroll
                for (int nj = 0; nj < 2; nj++)
                    xph[g][nj] = *(const __half2*)&g_xp16[(size_t)(g * Hq + u) * NB
                                                          + tn * Bq + c0 + nj * 8];

            // ---- wait: all CTAs published step s+1 ----
            if (tid == 0) {
                while (ld_acq(&g_gen) < (unsigned)(s + 1)) { }
            }
            __syncthreads();
        }
    }
}

// ---------------------------------------------------------------------------
// Final linear
// ---------------------------------------------------------------------------
__global__ __launch_bounds__(256) void k_lin(const float* __restrict__ Wlin,
                                             const float* __restrict__ blin,
                                             float* __restrict__ out) {
    int gid = blockIdx.x * blockDim.x + threadIdx.x;
    int b = gid & (Bq - 1);
    int tgt = gid >> 7;
    float acc = blin[tgt];
    const float* __restrict__ wrow = Wlin + (size_t)tgt * Hq;
#pragma unroll 8
    for (int k = 0; k < Hq; k++) {
        acc += g_hf[k * Bq + b] * wrow[k];
    }
    out[(size_t)b * TGTq + tgt] = acc;
}

// ---------------------------------------------------------------------------
extern "C" void kernel_launch(void* const* d_in, const int* in_sizes, int n_in,
                              void* d_out, int out_size)
{
    const float* XW   = (const float*)d_in[0];
    const float* Wih  = (const float*)d_in[1];
    const float* Whh  = (const float*)d_in[2];
    const float* bih  = (const float*)d_in[3];
    const float* bhh  = (const float*)d_in[4];
    const float* Wlin = (const float*)d_in[5];
    const float* blin = (const float*)d_in[6];
    float* out = (float*)d_out;

    cudaFuncSetAttribute(k_xproj, cudaFuncAttributeMaxDynamicSharedMemorySize, SMEM_XP);
    cudaFuncSetAttribute(k_recur, cudaFuncAttributeMaxDynamicSharedMemorySize, SMEM_PERS);

    k_prep_w<<<G4, 256>>>(Wih, Whh);
    k_prep_x<<<NB, 256>>>(XW);
    k_init<<<128, 256>>>();
    k_xproj<<<dim3(32, 512, 1), 256, SMEM_XP>>>();
    k_recur<<<NCTA, 256, SMEM_PERS>>>(bih, bhh);
    k_lin<<<(Bq * TGTq) / 256, 256>>>(Wlin, blin, out);
}

// round 16
// speedup vs baseline: 2.5288x; 1.0093x over previous
#include <cuda_runtime.h>
#include <cuda_fp16.h>
#include <math.h>
#include <stdint.h>

#define Bq   128
#define Tq   512
#define Iq   512
#define Hq   1024
#define G4   4096
#define TGTq 512
#define NB   65536   // Tq * Bq
#define NCTA 128

// ---------------- persistent-kernel SMEM layout (A resident) -------------
#define PA          1032                   // A row pitch (halves): 1024 + 8 pad
#define A_SPL_B     (32 * PA * 2)          // 66048 B
// request >114KB so at most 1 CTA/SM is resident (co-residency insurance)
#define SMEM_PERS   (2 * A_SPL_B + 16)     // 132112 B (only first 66KB used)

// ---------------- xproj GEMM SMEM layout (single-fp16 W) -----------------
#define SP          72
#define REG_BYTES   (128 * SP * 2)         // 18432
#define XBUF_BYTES  (2 * REG_BYTES)        // Ah, Bx
#define SMEM_XP     (2 * XBUF_BYTES)       // 73728 B

// ---------------------------------------------------------------------------
// Persistent device scratch (no cudaMalloc allowed)
// ---------------------------------------------------------------------------
__device__ __align__(16) __half g_Wr_h[(size_t)G4 * Hq];   // Whh fp16 (single)
__device__ __align__(16) __half g_Wi_h[(size_t)G4 * Iq];   // Wih fp16 (single)
__device__ __align__(16) __half g_xh[(size_t)NB * Iq];     // x fp16 [t*128+b][i]
// h in mma-B-fragment layout (fp16 single): [buf][(kb*16+bg)*32+lane] = {r0,r1}
__device__ __align__(16) uint2 g_hB[2][64 * 16 * 32];
__device__ float g_hf[Hq * Bq];                            // [u][b] final h
__device__ __align__(16) __half g_xp16[(size_t)G4 * NB];   // x-proj fp16 [row][t*128+b]
__device__ unsigned g_cnt[8];                              // monotonic group counters
__device__ unsigned g_cnt2;                                // monotonic level-2 counter
__device__ unsigned g_gen;                                 // published step count

// ---------------------------------------------------------------------------
// PTX helpers (plain sm_100 feature set)
// ---------------------------------------------------------------------------
__device__ __forceinline__ uint32_t smem_u32(const void* p) {
    uint32_t a;
    asm("{ .reg .u64 t; cvta.to.shared.u64 t, %1; cvt.u32.u64 %0, t; }"
        : "=r"(a) : "l"(p));
    return a;
}
__device__ __forceinline__ void ldsm4(uint32_t* r, uint32_t addr) {
    asm volatile("ldmatrix.sync.aligned.m8n8.x4.shared.b16 {%0,%1,%2,%3}, [%4];"
                 : "=r"(r[0]), "=r"(r[1]), "=r"(r[2]), "=r"(r[3]) : "r"(addr));
}
__device__ __forceinline__ void mma16816(float* c, const uint32_t* a, const uint32_t* b) {
    asm volatile(
        "mma.sync.aligned.m16n8k16.row.col.f32.f16.f16.f32 "
        "{%0,%1,%2,%3}, {%4,%5,%6,%7}, {%8,%9}, {%0,%1,%2,%3};"
        : "+f"(c[0]), "+f"(c[1]), "+f"(c[2]), "+f"(c[3])
        : "r"(a[0]), "r"(a[1]), "r"(a[2]), "r"(a[3]), "r"(b[0]), "r"(b[1]));
}
__device__ __forceinline__ void ldg_cg_v2(uint2& v, const uint2* p) {
    asm volatile("ld.global.cg.v2.u32 {%0,%1}, [%2];"
                 : "=r"(v.x), "=r"(v.y) : "l"(p));
}
__device__ __forceinline__ unsigned ld_acq(const unsigned* p) {
    unsigned v;
    asm volatile("ld.acquire.gpu.global.u32 %0, [%1];" : "=r"(v) : "l"(p) : "memory");
    return v;
}
#define CP16(d, s) \
    asm volatile("cp.async.cg.shared.global [%0], [%1], 16;" :: "r"(d), "l"(s) : "memory")
#define CPCOMMIT() asm volatile("cp.async.commit_group;" ::: "memory")

__device__ __forceinline__ float sigf(float x) {
    return __fdividef(1.0f, 1.0f + __expf(-x));
}
__device__ __forceinline__ float tanhfast(float x) {
    return __fdividef(2.0f, 1.0f + __expf(-2.0f * x)) - 1.0f;
}

// ---------------------------------------------------------------------------
// Prep kernels
// ---------------------------------------------------------------------------
__global__ void k_prep_w(const float* __restrict__ Wih, const float* __restrict__ Whh) {
    int r = blockIdx.x;
    for (int k = threadIdx.x; k < Hq; k += 256) {
        g_Wr_h[(size_t)r * Hq + k] = __float2half_rn(Whh[(size_t)r * Hq + k]);
    }
    for (int k = threadIdx.x; k < Iq; k += 256) {
        g_Wi_h[(size_t)r * Iq + k] = __float2half_rn(Wih[(size_t)r * Iq + k]);
    }
}

__global__ void k_prep_x(const float* __restrict__ XW) {
    int bx = blockIdx.x;          // t*128 + b
    int t = bx >> 7, b = bx & 127;
    const float* __restrict__ src = XW + ((size_t)b * Tq + t) * Iq;
    size_t doff = (size_t)bx * Iq;
    for (int i = threadIdx.x; i < Iq; i += 256) {
        g_xh[doff + i] = __float2half_rn(src[i]);
    }
}

__global__ void k_init() {
    if (blockIdx.x == 0 && threadIdx.x < 8) g_cnt[threadIdx.x] = 0;
    if (blockIdx.x == 0 && threadIdx.x == 8) { g_cnt2 = 0; g_gen = 0; }
    int n = 64 * 16 * 32;
    uint2 z = make_uint2(0, 0);
    for (int i = blockIdx.x * blockDim.x + threadIdx.x; i < n;
         i += gridDim.x * blockDim.x) {
        g_hB[0][i] = z;
        g_hB[1][i] = z;
    }
}

// ---------------------------------------------------------------------------
// x-projection GEMM (single fp16): g_xp16 = fp16(Wih * x^T)
// grid (32, 512): C tile 128(M of 4096) x 128(N of 65536), K=512.
// B fragments loaded pairwise via ldsm4 (lanes 16-31 -> nj+1 tile).
// ---------------------------------------------------------------------------
__global__ __launch_bounds__(256) void k_xproj() {
    extern __shared__ __align__(128) uint8_t smem[];
    const uint32_t sb = smem_u32(smem);
    const int tid = threadIdx.x;
    const int L = tid & 31, w = tid >> 5;
    const int mw = w & 3, nw = w >> 2;   // warp tile M32 x N64

    const int mrow0 = blockIdx.x * 128;
    const int nrow0 = blockIdx.y * 128;
    const int lsc = tid & 7;

    const uint32_t a_off = ((mw * 32 + (L & 15)) * SP + (L >> 4) * 8) * 2;
    // B pair-ldsm4 lane map: lanes 0-7 rows nj*8+0..7 k0; 8-15 same rows k8;
    // 16-23 rows (nj+1)*8 k0; 24-31 k8.
    const uint32_t b_off =
        (((nw * 64 + (L & 7) + ((L >> 4) << 3)) * SP + ((L >> 3) & 1) * 8)) * 2;

    float acc[2][8][4];
#pragma unroll
    for (int mi = 0; mi < 2; mi++)
#pragma unroll
        for (int nj = 0; nj < 8; nj++)
#pragma unroll
            for (int q = 0; q < 4; q++) acc[mi][nj][q] = 0.0f;

    auto load_chunk = [&](int buf, int ch) {
        const int gk = ch * 64 + lsc * 8;
        const uint32_t dstbase = sb + buf * XBUF_BYTES;
#pragma unroll
        for (int i = 0; i < 4; i++) {
            int row = (tid >> 3) + i * 32;
            uint32_t doff = (uint32_t)row * 144 + lsc * 16;
            size_t ao = (size_t)(mrow0 + row) * Iq + gk;
            size_t bo = (size_t)(nrow0 + row) * Iq + gk;
            CP16(dstbase + 0 * REG_BYTES + doff, g_Wi_h + ao);
            CP16(dstbase + 1 * REG_BYTES + doff, g_xh + bo);
        }
        CPCOMMIT();
    };

    load_chunk(0, 0);
    load_chunk(1, 1);
    for (int c = 0; c < 8; c++) {
        if (c < 7) asm volatile("cp.async.wait_group 1;" ::: "memory");
        else       asm volatile("cp.async.wait_group 0;" ::: "memory");
        __syncthreads();
        const uint32_t base = sb + (c & 1) * XBUF_BYTES;
#pragma unroll
        for (int ki = 0; ki < 4; ki++) {
            uint32_t ah[2][4], bh[8][2];
#pragma unroll
            for (int mi = 0; mi < 2; mi++) {
                uint32_t ad = base + a_off + (mi * 16 * SP + ki * 16) * 2;
                ldsm4(ah[mi], ad);
            }
#pragma unroll
            for (int njp = 0; njp < 4; njp++) {
                uint32_t r4[4];
                uint32_t bd = base + 1 * REG_BYTES + b_off
                            + (njp * 16 * SP + ki * 16) * 2;
                ldsm4(r4, bd);
                bh[njp * 2 + 0][0] = r4[0]; bh[njp * 2 + 0][1] = r4[1];
                bh[njp * 2 + 1][0] = r4[2]; bh[njp * 2 + 1][1] = r4[3];
            }
#pragma unroll
            for (int mi = 0; mi < 2; mi++)
#pragma unroll
                for (int nj = 0; nj < 8; nj++) {
                    mma16816(acc[mi][nj], ah[mi], bh[nj]);
                }
        }
        if (c + 2 < 8) {
            __syncthreads();
            load_chunk(c & 1, c + 2);
        }
    }

#pragma unroll
    for (int mi = 0; mi < 2; mi++)
#pragma unroll
        for (int nj = 0; nj < 8; nj++) {
            int row = mrow0 + mw * 32 + mi * 16 + (L >> 2);
            int col = nrow0 + nw * 64 + nj * 8 + (L & 3) * 2;
            __half* p = g_xp16 + (size_t)row * NB + col;
            __stcs((__half2*)p,
                   __floats2half2_rn(acc[mi][nj][0], acc[mi][nj][1]));
            __stcs((__half2*)(p + 8 * NB),
                   __floats2half2_rn(acc[mi][nj][2], acc[mi][nj][3]));
        }
}

// ---------------------------------------------------------------------------
// Persistent recurrence (R14 structure; B ring distance 5, 6 slots).
// CTA c owns units u = c*8..c*8+7 (32 gate rows). A = Whh fp16 resident
// in SMEM; B (h) via ld.cg.v2 register ring. Cell state in registers;
// next h written in B-fragment layout. Barrier: arrive after h-publish,
// xp prefetch in the window, wait just before next step.
// ---------------------------------------------------------------------------
__global__ __launch_bounds__(256, 1) void k_recur(const float* __restrict__ bih,
                                                  const float* __restrict__ bhh) {
    extern __shared__ __align__(128) uint8_t smem[];
    const uint32_t sb = smem_u32(smem);
    const int tid = threadIdx.x;
    const int c = blockIdx.x;
    const int L = tid & 31;
    const int nw = tid >> 5;             // warp = N group of 16 batch cols

    // ---- load resident A (Whh fp16) : 32 rows x 1024 halves ----
    {
        int row32 = tid >> 3;            // 0..31  (row = g*8 + j)
        int g = row32 >> 3, j = row32 & 7;
        size_t grow = ((size_t)g * Hq + c * 8 + j) * Hq;
        int seg = tid & 7;
#pragma unroll
        for (int it = 0; it < 16; it++) {
            int s16 = seg + it * 8;
            uint32_t doff = (uint32_t)row32 * (PA * 2) + s16 * 16;
            CP16(sb + doff, g_Wr_h + grow + s16 * 8);
        }
        CPCOMMIT();
    }

    // per-thread cell mapping (identical to R10/R14)
    const int j = (L >> 2) & 7;          // unit within CTA
    const int u = c * 8 + j;             // global hidden unit
    const int c0 = nw * 16 + (L & 3) * 2; // cells at c0,c0+1,c0+8,c0+9
    float bias[4], cc[4];
#pragma unroll
    for (int g = 0; g < 4; g++) {
        bias[g] = bih[g * Hq + u] + bhh[g * Hq + u];
        cc[g] = 0.0f;                    // cc indexed by (nj*2+e)
    }

    // producer store mapping for h fragments
    const int p_kb   = u >> 4;
    const int p_ln   = (u >> 1) & 3;
    const int p_boff = ((u >> 3) & 1) * 4 + (u & 1) * 2;

    const uint32_t aoff = (((L & 15) * PA + (L >> 4) * 8)) * 2;
    const int bgBase = nw * 2;

    asm volatile("cp.async.wait_group 0;" ::: "memory");
    __syncthreads();

    // xp prefetch for first step (fp16 pairs)
    __half2 xph[4][2];
#pragma unroll
    for (int g = 0; g < 4; g++)
#pragma unroll
        for (int nj = 0; nj < 2; nj++)
            xph[g][nj] = *(const __half2*)&g_xp16[(size_t)(g * Hq + u) * NB
                                                  + (Tq - 1) * Bq + c0 + nj * 8];

    for (int s = 0; s < Tq; s++) {
        const uint2* __restrict__ hBin = g_hB[s & 1];
        uint2* __restrict__ hBout      = g_hB[(s + 1) & 1];

        float acc[2][2][4];
#pragma unroll
        for (int mi = 0; mi < 2; mi++)
#pragma unroll
            for (int nj = 0; nj < 2; nj++)
#pragma unroll
                for (int q = 0; q < 4; q++) acc[mi][nj][q] = 0.0f;

        uint2 Bp[6][8];   // 6-slot ring (prefetch distance 5), compile-time idx

#define LOADB(G, SLOT)                                                        \
        {                                                                     \
            _Pragma("unroll")                                                 \
            for (int kk = 0; kk < 4; kk++)                                    \
                _Pragma("unroll")                                             \
                for (int nj = 0; nj < 2; nj++)                                \
                    ldg_cg_v2(Bp[SLOT][kk * 2 + nj],                          \
                              hBin + (((G) * 4 + kk) * 16 + bgBase + nj) * 32 + L); \
        }

        LOADB(0, 0); LOADB(1, 1); LOADB(2, 2); LOADB(3, 3); LOADB(4, 4);

#pragma unroll
        for (int g = 0; g < 16; g++) {
            if (g + 5 < 16) {
                const int ng = g + 5;
                const int ns = ng % 6;
                LOADB(ng, ns);
            }
            const int slot = g % 6;
#pragma unroll
            for (int kk = 0; kk < 4; kk++) {
                const int k = (g * 4 + kk) * 16;
                uint32_t ah[2][4];
#pragma unroll
                for (int mi = 0; mi < 2; mi++) {
                    uint32_t ad = sb + aoff + (uint32_t)(mi * 16 * PA + k) * 2;
                    ldsm4(ah[mi], ad);
                }
#pragma unroll
                for (int nj = 0; nj < 2; nj++) {
                    uint32_t bh[2] = { Bp[slot][kk * 2 + nj].x, Bp[slot][kk * 2 + nj].y };
#pragma unroll
                    for (int mi = 0; mi < 2; mi++) {
                        mma16816(acc[mi][nj], ah[mi], bh);
                    }
                }
            }
        }
#undef LOADB

        // ---- register-local cell update for 4 (batch) positions ----
        const bool last = (s == Tq - 1);
#pragma unroll
        for (int nj = 0; nj < 2; nj++) {
            float2 x0 = __half22float2(xph[0][nj]);
            float2 x1 = __half22float2(xph[1][nj]);
            float2 x2 = __half22float2(xph[2][nj]);
            float2 x3 = __half22float2(xph[3][nj]);
#pragma unroll
            for (int e = 0; e < 2; e++) {
                int b = c0 + nj * 8 + e;
                float xpi = e ? x0.y : x0.x;
                float xpf = e ? x1.y : x1.x;
                float xpg = e ? x2.y : x2.x;
                float xpo = e ? x3.y : x3.x;
                float ig = sigf(acc[0][nj][e]     + xpi + bias[0]);
                float fg = sigf(acc[0][nj][2 + e] + xpf + bias[1]);
                float gg = tanhfast(acc[1][nj][e]    + xpg + bias[2]);
                float og = sigf(acc[1][nj][2 + e] + xpo + bias[3]);
                int ci = nj * 2 + e;
                float cv = fg * cc[ci] + ig * gg;
                cc[ci] = cv;
                float h = og * tanhfast(cv);
                int lane = ((b & 7) << 2) | p_ln;
                char* qp = (char*)&hBout[(p_kb * 16 + (b >> 3)) * 32 + lane];
                *(__half*)(qp + p_boff) = __float2half_rn(h);
                if (last) g_hf[u * Bq + b] = h;
            }
        }

        if (!last) {
            // ---- arrive: h stores visible, bump monotonic counters ----
            __threadfence();
            __syncthreads();
            if (tid == 0) {
                unsigned grp = (unsigned)c >> 4;
                unsigned old = atomicAdd(&g_cnt[grp], 1u);
                if ((old & 15u) == 15u) {
                    unsigned o2 = atomicAdd(&g_cnt2, 1u);
                    if ((o2 & 7u) == 7u) {
                        asm volatile("st.release.gpu.global.u32 [%0], %1;"
                                     :: "l"(&g_gen), "r"((unsigned)(s + 1)) : "memory");
                    }
                }
            }

            // ---- overlap window: next step's xp prefetch (fp16) ----
            const int tn = Tq - 2 - s;
#pragma unroll
            for (int g = 0; g < 4; g++)
#pragma unroll
                for (int nj = 0; nj < 2; nj++)
                    xph[g][nj] = *(const __half2*)&g_xp16[(size_t)(g * Hq + u) * NB
                                                          + tn * Bq + c0 + nj * 8];

            // ---- wait: all CTAs published step s+1 ----
            if (tid == 0) {
                while (ld_acq(&g_gen) < (unsigned)(s + 1)) { }
            }
            __syncthreads();
        }
    }
}

// ---------------------------------------------------------------------------
// Final linear
// ---------------------------------------------------------------------------
__global__ __launch_bounds__(256) void k_lin(const float* __restrict__ Wlin,
                                             const float* __restrict__ blin,
                                             float* __restrict__ out) {
    int gid = blockIdx.x * blockDim.x + threadIdx.x;
    int b = gid & (Bq - 1);
    int tgt = gid >> 7;
    float acc = blin[tgt];
    const float* __restrict__ wrow = Wlin + (size_t)tgt * Hq;
#pragma unroll 8
    for (int k = 0; k < Hq; k++) {
        acc += g_hf[k * Bq + b] * wrow[k];
    }
    out[(size_t)b * TGTq + tgt] = acc;
}

// ---------------------------------------------------------------------------
extern "C" void kernel_launch(void* const* d_in, const int* in_sizes, int n_in,
                              void* d_out, int out_size)
{
    const float* XW   = (const float*)d_in[0];
    const float* Wih  = (const float*)d_in[1];
    const float* Whh  = (const float*)d_in[2];
    const float* bih  = (const float*)d_in[3];
    const float* bhh  = (const float*)d_in[4];
    const float* Wlin = (const float*)d_in[5];
    const float* blin = (const float*)d_in[6];
    float* out = (float*)d_out;

    cudaFuncSetAttribute(k_xproj, cudaFuncAttributeMaxDynamicSharedMemorySize, SMEM_XP);
    cudaFuncSetAttribute(k_recur, cudaFuncAttributeMaxDynamicSharedMemorySize, SMEM_PERS);

    k_prep_w<<<G4, 256>>>(Wih, Whh);
    k_prep_x<<<NB, 256>>>(XW);
    k_init<<<128, 256>>>();
    k_xproj<<<dim3(32, 512, 1), 256, SMEM_XP>>>();
    k_recur<<<NCTA, 256, SMEM_PERS>>>(bih, bhh);
    k_lin<<<(Bq * TGTq) / 256, 256>>>(Wlin, blin, out);
}

// round 17
// speedup vs baseline: 2.5395x; 1.0042x over previous
#include <cuda_runtime.h>
#include <cuda_fp16.h>
#include <math.h>
#include <stdint.h>

#define Bq   128
#define Tq   512
#define Iq   512
#define Hq   1024
#define G4   4096
#define TGTq 512
#define NB   65536   // Tq * Bq
#define NCTA 128

// ---------------- persistent-kernel SMEM layout (A resident) -------------
#define PA          1032                   // Whh row pitch (halves)
#define PAX         520                    // Wih row pitch (halves)
#define WIH_OFF     (32 * PA * 2)          // 66048
// Whh 66048 + Wih 33280 = 99328 used; request >114KB for 1 CTA/SM
#define SMEM_PERS   132112

// ---------------------------------------------------------------------------
// Persistent device scratch (no cudaMalloc allowed)
// ---------------------------------------------------------------------------
__device__ __align__(16) __half g_Wr_h[(size_t)G4 * Hq];   // Whh fp16
__device__ __align__(16) __half g_Wi_h[(size_t)G4 * Iq];   // Wih fp16
// h in mma-B-fragment layout: [buf][(kb*16+bg)*32+lane] = {r0,r1}
__device__ __align__(16) uint2 g_hB[2][64 * 16 * 32];
// x in the SAME B-fragment layout, per timestep: [t][(kb*16+bg)*32+lane]
__device__ __align__(16) uint2 g_xB[(size_t)Tq * 16384];
__device__ float g_hf[Hq * Bq];                            // [u][b] final h
__device__ unsigned g_cnt[8];                              // monotonic counters
__device__ unsigned g_cnt2;
__device__ unsigned g_gen;                                 // published step count

// ---------------------------------------------------------------------------
// PTX helpers (plain sm_100 feature set)
// ---------------------------------------------------------------------------
__device__ __forceinline__ uint32_t smem_u32(const void* p) {
    uint32_t a;
    asm("{ .reg .u64 t; cvta.to.shared.u64 t, %1; cvt.u32.u64 %0, t; }"
        : "=r"(a) : "l"(p));
    return a;
}
__device__ __forceinline__ void ldsm4(uint32_t* r, uint32_t addr) {
    asm volatile("ldmatrix.sync.aligned.m8n8.x4.shared.b16 {%0,%1,%2,%3}, [%4];"
                 : "=r"(r[0]), "=r"(r[1]), "=r"(r[2]), "=r"(r[3]) : "r"(addr));
}
__device__ __forceinline__ void mma16816(float* c, const uint32_t* a, const uint32_t* b) {
    asm volatile(
        "mma.sync.aligned.m16n8k16.row.col.f32.f16.f16.f32 "
        "{%0,%1,%2,%3}, {%4,%5,%6,%7}, {%8,%9}, {%0,%1,%2,%3};"
        : "+f"(c[0]), "+f"(c[1]), "+f"(c[2]), "+f"(c[3])
        : "r"(a[0]), "r"(a[1]), "r"(a[2]), "r"(a[3]), "r"(b[0]), "r"(b[1]));
}
__device__ __forceinline__ void ldg_cg_v2(uint2& v, const uint2* p) {
    asm volatile("ld.global.cg.v2.u32 {%0,%1}, [%2];"
                 : "=r"(v.x), "=r"(v.y) : "l"(p));
}
__device__ __forceinline__ unsigned ld_acq(const unsigned* p) {
    unsigned v;
    asm volatile("ld.acquire.gpu.global.u32 %0, [%1];" : "=r"(v) : "l"(p) : "memory");
    return v;
}
__device__ __forceinline__ unsigned atom_add_acqrel(unsigned* p, unsigned v) {
    unsigned old;
    asm volatile("atom.acq_rel.gpu.global.add.u32 %0, [%1], %2;"
                 : "=r"(old) : "l"(p), "r"(v) : "memory");
    return old;
}
#define CP16(d, s) \
    asm volatile("cp.async.cg.shared.global [%0], [%1], 16;" :: "r"(d), "l"(s) : "memory")
#define CPCOMMIT() asm volatile("cp.async.commit_group;" ::: "memory")

__device__ __forceinline__ float sigf(float x) {
    return __fdividef(1.0f, 1.0f + __expf(-x));
}
__device__ __forceinline__ float tanhfast(float x) {
    return __fdividef(2.0f, 1.0f + __expf(-2.0f * x)) - 1.0f;
}

// ---------------------------------------------------------------------------
// Prep kernels
// ---------------------------------------------------------------------------
__global__ void k_prep_w(const float* __restrict__ Wih, const float* __restrict__ Whh) {
    int r = blockIdx.x;
    for (int k = threadIdx.x; k < Hq; k += 256) {
        g_Wr_h[(size_t)r * Hq + k] = __float2half_rn(Whh[(size_t)r * Hq + k]);
    }
    for (int k = threadIdx.x; k < Iq; k += 256) {
        g_Wi_h[(size_t)r * Iq + k] = __float2half_rn(Wih[(size_t)r * Iq + k]);
    }
}

// Pack x[t] into B-fragment layout (identical mapping to the h producer):
// word w: kb = w>>9, bg = (w>>5)&15, L = w&31; b = bg*8 + (L>>2);
// i0 = kb*16 + (L&3)*2; halves {i0, i0+1 | i0+8, i0+9}.
__global__ void k_prep_xB(const float* __restrict__ XW) {
    int t = blockIdx.x;
    uint2* __restrict__ dst = g_xB + (size_t)t * 16384;
    for (int w = threadIdx.x; w < 16384; w += 256) {
        int kb = w >> 9, bg = (w >> 5) & 15, L = w & 31;
        int b = bg * 8 + (L >> 2);
        int i0 = kb * 16 + (L & 3) * 2;
        const float* __restrict__ src = XW + ((size_t)b * Tq + t) * Iq;
        __half2 lo = __floats2half2_rn(src[i0],     src[i0 + 1]);
        __half2 hi = __floats2half2_rn(src[i0 + 8], src[i0 + 9]);
        uint2 v;
        v.x = *(const uint32_t*)&lo;
        v.y = *(const uint32_t*)&hi;
        dst[w] = v;
    }
}

__global__ void k_init() {
    if (blockIdx.x == 0 && threadIdx.x < 8) g_cnt[threadIdx.x] = 0;
    if (blockIdx.x == 0 && threadIdx.x == 8) { g_cnt2 = 0; g_gen = 0; }
    int n = 64 * 16 * 32;
    uint2 z = make_uint2(0, 0);
    for (int i = blockIdx.x * blockDim.x + threadIdx.x; i < n;
         i += gridDim.x * blockDim.x) {
        g_hB[0][i] = z;
        g_hB[1][i] = z;
    }
}

// ---------------------------------------------------------------------------
// Persistent fused recurrence: gates = Wih*x_t + Whh*h (K = 512 + 1024).
// CTA c owns units u = c*8..c*8+7 (32 gate rows). Whh AND Wih resident in
// SMEM. x B-fragments (no dependency) prefetched during the barrier window
// and computed FIRST each step — h-ring loads fill behind them. Barrier:
// CG-style (no per-thread fence; acq_rel atomic tree by tid0).
// ---------------------------------------------------------------------------
__global__ __launch_bounds__(256, 1) void k_recur(const float* __restrict__ bih,
                                                  const float* __restrict__ bhh) {
    extern __shared__ __align__(128) uint8_t smem[];
    const uint32_t sb = smem_u32(smem);
    const int tid = threadIdx.x;
    const int c = blockIdx.x;
    const int L = tid & 31;
    const int nw = tid >> 5;             // warp = N group of 16 batch cols

    // ---- resident A tiles: Whh (32x1024) + Wih (32x512), fp16 ----
    {
        int row32 = tid >> 3;            // 0..31  (row = g*8 + j)
        int g = row32 >> 3, jj = row32 & 7;
        size_t growr = ((size_t)g * Hq + c * 8 + jj) * Hq;
        size_t growi = ((size_t)g * Hq + c * 8 + jj) * Iq;
        int seg = tid & 7;
#pragma unroll
        for (int it = 0; it < 16; it++) {
            int s16 = seg + it * 8;
            CP16(sb + (uint32_t)row32 * (PA * 2) + s16 * 16, g_Wr_h + growr + s16 * 8);
        }
#pragma unroll
        for (int it = 0; it < 8; it++) {
            int s16 = seg + it * 8;      // 0..63
            CP16(sb + WIH_OFF + (uint32_t)row32 * (PAX * 2) + s16 * 16,
                 g_Wi_h + growi + s16 * 8);
        }
        CPCOMMIT();
    }

    // per-thread cell mapping (identical to R10..R16)
    const int j = (L >> 2) & 7;          // unit within CTA
    const int u = c * 8 + j;             // global hidden unit
    const int c0 = nw * 16 + (L & 3) * 2; // cells at c0,c0+1,c0+8,c0+9
    float bias[4], cc[4];
#pragma unroll
    for (int g = 0; g < 4; g++) {
        bias[g] = bih[g * Hq + u] + bhh[g * Hq + u];
        cc[g] = 0.0f;                    // cc indexed by (nj*2+e)
    }

    // producer store mapping for h fragments
    const int p_kb   = u >> 4;
    const int p_ln   = (u >> 1) & 3;
    const int p_boff = ((u >> 3) & 1) * 4 + (u & 1) * 2;

    const uint32_t aoff  = (((L & 15) * PA  + (L >> 4) * 8)) * 2;
    const uint32_t aoffx = (((L & 15) * PAX + (L >> 4) * 8)) * 2;
    const int bgBase = nw * 2;

    asm volatile("cp.async.wait_group 0;" ::: "memory");
    __syncthreads();

    uint2 Xp[3][8];   // x-ring: 3 slots, prefetch distance 2

#define LOADX(PTR, G, SLOT)                                                   \
    {                                                                         \
        _Pragma("unroll")                                                     \
        for (int kk = 0; kk < 4; kk++)                                        \
            _Pragma("unroll")                                                 \
            for (int nj = 0; nj < 2; nj++)                                    \
                ldg_cg_v2(Xp[SLOT][kk * 2 + nj],                              \
                          (PTR) + (((G) * 4 + kk) * 16 + bgBase + nj) * 32 + L); \
    }

    // prefetch x groups 0,1 for step 0 (t = Tq-1)
    {
        const uint2* xb0 = g_xB + (size_t)(Tq - 1) * 16384;
        LOADX(xb0, 0, 0);
        LOADX(xb0, 1, 1);
    }

    for (int s = 0; s < Tq; s++) {
        const int t = Tq - 1 - s;
        const uint2* __restrict__ hBin = g_hB[s & 1];
        uint2* __restrict__ hBout      = g_hB[(s + 1) & 1];
        const uint2* __restrict__ xbt  = g_xB + (size_t)t * 16384;

        float acc[2][2][4];
#pragma unroll
        for (int mi = 0; mi < 2; mi++)
#pragma unroll
            for (int nj = 0; nj < 2; nj++)
#pragma unroll
                for (int q = 0; q < 4; q++) acc[mi][nj][q] = 0.0f;

        uint2 Bp[4][8];   // h-ring: 4 slots, prefetch distance 3

#define LOADB(G, SLOT)                                                        \
        {                                                                     \
            _Pragma("unroll")                                                 \
            for (int kk = 0; kk < 4; kk++)                                    \
                _Pragma("unroll")                                             \
                for (int nj = 0; nj < 2; nj++)                                \
                    ldg_cg_v2(Bp[SLOT][kk * 2 + nj],                          \
                              hBin + (((G) * 4 + kk) * 16 + bgBase + nj) * 32 + L); \
        }

        // issue h-ring fill now — lands while x groups compute
        LOADB(0, 0); LOADB(1, 1); LOADB(2, 2);

        // ---- x part: 8 groups (K = 512), Wih resident ----
#pragma unroll
        for (int gx = 0; gx < 8; gx++) {
            if (gx + 2 < 8) {
                const int ng = gx + 2;
                const int ns = ng % 3;
                LOADX(xbt, ng, ns);
            }
            const int slot = gx % 3;
#pragma unroll
            for (int kk = 0; kk < 4; kk++) {
                const int k = (gx * 4 + kk) * 16;
                uint32_t ah[2][4];
#pragma unroll
                for (int mi = 0; mi < 2; mi++) {
                    uint32_t ad = sb + WIH_OFF + aoffx
                                + (uint32_t)(mi * 16 * PAX + k) * 2;
                    ldsm4(ah[mi], ad);
                }
#pragma unroll
                for (int nj = 0; nj < 2; nj++) {
                    uint32_t bh[2] = { Xp[slot][kk * 2 + nj].x, Xp[slot][kk * 2 + nj].y };
#pragma unroll
                    for (int mi = 0; mi < 2; mi++) {
                        mma16816(acc[mi][nj], ah[mi], bh);
                    }
                }
            }
        }

        // ---- h part: 16 groups (K = 1024), Whh resident ----
#pragma unroll
        for (int g = 0; g < 16; g++) {
            if (g + 3 < 16) {
                const int ng = g + 3;
                const int ns = ng & 3;
                LOADB(ng, ns);
            }
            const int slot = g & 3;
#pragma unroll
            for (int kk = 0; kk < 4; kk++) {
                const int k = (g * 4 + kk) * 16;
                uint32_t ah[2][4];
#pragma unroll
                for (int mi = 0; mi < 2; mi++) {
                    uint32_t ad = sb + aoff + (uint32_t)(mi * 16 * PA + k) * 2;
                    ldsm4(ah[mi], ad);
                }
#pragma unroll
                for (int nj = 0; nj < 2; nj++) {
                    uint32_t bh[2] = { Bp[slot][kk * 2 + nj].x, Bp[slot][kk * 2 + nj].y };
#pragma unroll
                    for (int mi = 0; mi < 2; mi++) {
                        mma16816(acc[mi][nj], ah[mi], bh);
                    }
                }
            }
        }
#undef LOADB

        // ---- register-local cell update for 4 (batch) positions ----
        const bool last = (s == Tq - 1);
#pragma unroll
        for (int nj = 0; nj < 2; nj++)
#pragma unroll
            for (int e = 0; e < 2; e++) {
                int b = c0 + nj * 8 + e;
                float ig = sigf(acc[0][nj][e]     + bias[0]);
                float fg = sigf(acc[0][nj][2 + e] + bias[1]);
                float gg = tanhfast(acc[1][nj][e]    + bias[2]);
                float og = sigf(acc[1][nj][2 + e] + bias[3]);
                int ci = nj * 2 + e;
                float cv = fg * cc[ci] + ig * gg;
                cc[ci] = cv;
                float h = og * tanhfast(cv);
                int lane = ((b & 7) << 2) | p_ln;
                char* qp = (char*)&hBout[(p_kb * 16 + (b >> 3)) * 32 + lane];
                *(__half*)(qp + p_boff) = __float2half_rn(h);
                if (last) g_hf[u * Bq + b] = h;
            }

        if (!last) {
            // ---- arrive: CG-style (barrier makes h stores observed;
            //      acq_rel atomics carry them to gpu scope) ----
            __syncthreads();
            if (tid == 0) {
                unsigned grp = (unsigned)c >> 4;
                unsigned old = atom_add_acqrel(&g_cnt[grp], 1u);
                if ((old & 15u) == 15u) {
                    unsigned o2 = atom_add_acqrel(&g_cnt2, 1u);
                    if ((o2 & 7u) == 7u) {
                        asm volatile("st.release.gpu.global.u32 [%0], %1;"
                                     :: "l"(&g_gen), "r"((unsigned)(s + 1)) : "memory");
                    }
                }
            }

            // ---- overlap window: prefetch next step's x groups 0,1 ----
            {
                const uint2* xbn = g_xB + (size_t)(t - 1) * 16384;
                LOADX(xbn, 0, 0);
                LOADX(xbn, 1, 1);
            }

            // ---- wait: all CTAs published step s+1 ----
            if (tid == 0) {
                while (ld_acq(&g_gen) < (unsigned)(s + 1)) { }
            }
            __syncthreads();
        }
    }
#undef LOADX
}

// ---------------------------------------------------------------------------
// Final linear
// ---------------------------------------------------------------------------
__global__ __launch_bounds__(256) void k_lin(const float* __restrict__ Wlin,
                                             const float* __restrict__ blin,
                                             float* __restrict__ out) {
    int gid = blockIdx.x * blockDim.x + threadIdx.x;
    int b = gid & (Bq - 1);
    int tgt = gid >> 7;
    float acc = blin[tgt];
    const float* __restrict__ wrow = Wlin + (size_t)tgt * Hq;
#pragma unroll 8
    for (int k = 0; k < Hq; k++) {
        acc += g_hf[k * Bq + b] * wrow[k];
    }
    out[(size_t)b * TGTq + tgt] = acc;
}

// ---------------------------------------------------------------------------
extern "C" void kernel_launch(void* const* d_in, const int* in_sizes, int n_in,
                              void* d_out, int out_size)
{
    const float* XW   = (const float*)d_in[0];
    const float* Wih  = (const float*)d_in[1];
    const float* Whh  = (const float*)d_in[2];
    const float* bih  = (const float*)d_in[3];
    const float* bhh  = (const float*)d_in[4];
    const float* Wlin = (const float*)d_in[5];
    const float* blin = (const float*)d_in[6];
    float* out = (float*)d_out;

    cudaFuncSetAttribute(k_recur, cudaFuncAttributeMaxDynamicSharedMemorySize, SMEM_PERS);

    k_prep_w<<<G4, 256>>>(Wih, Whh);
    k_prep_xB<<<Tq, 256>>>(XW);
    k_init<<<128, 256>>>();
    k_recur<<<NCTA, 256, SMEM_PERS>>>(bih, bhh);
    k_lin<<<(Bq * TGTq) / 256, 256>>>(Wlin, blin, out);
}